// round 4
// baseline (speedup 1.0000x reference)
#include <cuda_runtime.h>

// ---------------- problem constants ----------------
#define TBS   128          // T*B = 4*32
#define SEQ   81           // 9*9
#define CH    128          // width C
#define MROWS (TBS*SEQ)    // 10368 rows
#define NQKV  384          // 3*C
#define EPSLN 1e-5f

typedef unsigned long long ull;

// ---------------- scratch (static device globals; no allocation) ------------
__device__ float  g_h  [MROWS*CH];    // residual stream
__device__ float2 g_stats[MROWS];     // per-row (mu, rstd) of g_h
__device__ float  g_qkv[MROWS*NQKV];  // qkv projection
__device__ float  g_att[MROWS*CH];    // attention output

// ---------------- packed f32x2 helpers --------------------------------------
__device__ __forceinline__ ull fma2(ull a, ull b, ull c) {
    ull d;
    asm("fma.rn.f32x2 %0, %1, %2, %3;" : "=l"(d) : "l"(a), "l"(b), "l"(c));
    return d;
}
__device__ __forceinline__ void upk2(ull v, float& x, float& y) {
    unsigned int lo, hi;
    asm("mov.b64 {%0, %1}, %2;" : "=r"(lo), "=r"(hi) : "l"(v));
    x = __uint_as_float(lo);
    y = __uint_as_float(hi);
}
__device__ __forceinline__ float ex2(float x) {
    float r;
    asm("ex2.approx.f32 %0, %1;" : "=f"(r) : "f"(x));
    return r;
}

// ---------------- input projection + LN stats --------------------------------
// warp per row: h = x0*w0[c] + x1*w1[c] + b[c]; also write (mu, rstd).
__global__ void __launch_bounds__(256) inproj_kernel(const float* __restrict__ x,
                                                     const float* __restrict__ in_w,
                                                     const float* __restrict__ in_b) {
    int row  = blockIdx.x * 8 + (threadIdx.x >> 5);
    int lane = threadIdx.x & 31;
    float x0 = __ldg(&x[row * 2]);
    float x1 = __ldg(&x[row * 2 + 1]);
    float s = 0.f, ss = 0.f;
    float* hr = g_h + (size_t)row * CH;
#pragma unroll
    for (int j = 0; j < 4; j++) {
        int c = lane + 32 * j;
        float h = fmaf(x0, in_w[c], fmaf(x1, in_w[CH + c], in_b[c]));
        hr[c] = h;
        s += h;
        ss = fmaf(h, h, ss);
    }
#pragma unroll
    for (int o = 16; o; o >>= 1) {
        s  += __shfl_xor_sync(0xffffffffu, s, o);
        ss += __shfl_xor_sync(0xffffffffu, ss, o);
    }
    if (lane == 0) {
        float mu  = s * (1.0f / CH);
        float var = fmaf(-mu, mu, ss * (1.0f / CH));
        g_stats[row] = make_float2(mu, rsqrtf(var + EPSLN));
    }
}

// ---------------- fused LN + QKV GEMM ----------------------------------------
// A[m][k] = (g_h[m][k]-mu)*rstd*gam[k]+bet[k]; out = A@W + bias -> g_qkv.
// tile 128M x 96N, 256 threads, per-thread 8Mx6N via f32x2 row-pairs.
__global__ void __launch_bounds__(256) qkv_gemm(const float* __restrict__ W,
                                                const float* __restrict__ bias,
                                                const float* __restrict__ gam,
                                                const float* __restrict__ bet) {
    __shared__ float gsh[CH], bsh[CH];
    __shared__ __align__(16) float  As[16][128];
    __shared__ __align__(16) float2 Bs[16][96];

    int tid = threadIdx.x;
    if (tid < 128) gsh[tid] = gam[tid];
    else           bsh[tid - 128] = bet[tid - 128];

    int tx = tid & 15;             // col group: cols 6*tx .. +5
    int ty = tid >> 4;             // row group: rows 8*ty .. +7

    int arow = tid >> 1;           // A staging row 0..127
    int akh  = (tid & 1) * 8;      // A staging k-offset
    int bk   = tid >> 4;           // B staging k-row 0..15
    int bc   = (tid & 15) * 6;     // B staging col

    size_t gRow = (size_t)blockIdx.y * 128 + arow;
    const float* hp = g_h + gRow * CH;
    float2 st = g_stats[gRow];
    float c1 = st.y;               // rstd
    float c0 = -st.x * st.y;       // -mu*rstd
    const float* Bp = W + (size_t)bk * NQKV + blockIdx.x * 96 + bc;

    ull acc[4][6];
#pragma unroll
    for (int p = 0; p < 4; p++)
#pragma unroll
        for (int j = 0; j < 6; j++) acc[p][j] = 0ull;

    __syncthreads();               // gsh/bsh ready

    for (int k0 = 0; k0 < CH; k0 += 16) {
        float4 h0 = *(const float4*)(hp + k0 + akh);
        float4 h1 = *(const float4*)(hp + k0 + akh + 4);
        float2 b0 = *(const float2*)(Bp + (size_t)k0 * NQKV);
        float2 b1 = *(const float2*)(Bp + (size_t)k0 * NQKV + 2);
        float2 b2 = *(const float2*)(Bp + (size_t)k0 * NQKV + 4);
        float av[8] = {h0.x, h0.y, h0.z, h0.w, h1.x, h1.y, h1.z, h1.w};
#pragma unroll
        for (int j = 0; j < 8; j++) {
            int kk = akh + j;
            float ln = fmaf(av[j], c1, c0);
            As[kk][arow] = fmaf(ln, gsh[k0 + kk], bsh[k0 + kk]);
        }
        Bs[bk][bc + 0] = make_float2(b0.x, b0.x);
        Bs[bk][bc + 1] = make_float2(b0.y, b0.y);
        Bs[bk][bc + 2] = make_float2(b1.x, b1.x);
        Bs[bk][bc + 3] = make_float2(b1.y, b1.y);
        Bs[bk][bc + 4] = make_float2(b2.x, b2.x);
        Bs[bk][bc + 5] = make_float2(b2.y, b2.y);
        __syncthreads();
#pragma unroll
        for (int k = 0; k < 16; k++) {
            ulonglong2 a01 = *(const ulonglong2*)&As[k][8 * ty];
            ulonglong2 a23 = *(const ulonglong2*)&As[k][8 * ty + 4];
            ulonglong2 bb0 = *(const ulonglong2*)&Bs[k][6 * tx];
            ulonglong2 bb1 = *(const ulonglong2*)&Bs[k][6 * tx + 2];
            ulonglong2 bb2 = *(const ulonglong2*)&Bs[k][6 * tx + 4];
            ull ap[4] = {a01.x, a01.y, a23.x, a23.y};
            ull bp[6] = {bb0.x, bb0.y, bb1.x, bb1.y, bb2.x, bb2.y};
#pragma unroll
            for (int p = 0; p < 4; p++)
#pragma unroll
                for (int j = 0; j < 6; j++)
                    acc[p][j] = fma2(ap[p], bp[j], acc[p][j]);
        }
        __syncthreads();
    }

    int colBase = blockIdx.x * 96 + 6 * tx;
    float bb[6];
#pragma unroll
    for (int j = 0; j < 6; j++) bb[j] = bias[colBase + j];
#pragma unroll
    for (int p = 0; p < 4; p++) {
        size_t rowe = (size_t)blockIdx.y * 128 + 8 * ty + 2 * p;
        float lo[6], hi[6];
#pragma unroll
        for (int j = 0; j < 6; j++) {
            upk2(acc[p][j], lo[j], hi[j]);
            lo[j] += bb[j];
            hi[j] += bb[j];
        }
        float* o0 = g_qkv + rowe * NQKV + colBase;
        float* o1 = o0 + NQKV;
        *(float2*)(o0 + 0) = make_float2(lo[0], lo[1]);
        *(float2*)(o0 + 2) = make_float2(lo[2], lo[3]);
        *(float2*)(o0 + 4) = make_float2(lo[4], lo[5]);
        *(float2*)(o1 + 0) = make_float2(hi[0], hi[1]);
        *(float2*)(o1 + 2) = make_float2(hi[2], hi[3]);
        *(float2*)(o1 + 4) = make_float2(hi[4], hi[5]);
    }
}

// ---------------- fused per-channel attention (unchanged, proven) ------------
#define QT 9
#define KT 27
__global__ void __launch_bounds__(128, 8) attn_kernel() {
    int b  = blockIdx.y;
    int q0 = blockIdx.x * QT;
    int c  = threadIdx.x;

    __shared__ float ks[KT][CH];
    __shared__ float vs[KT][CH];

    const float* base = g_qkv + (size_t)b * SEQ * NQKV;
    const float LOG2E = 1.4426950408889634f;

    float qv[QT], num[QT], den[QT];
#pragma unroll
    for (int i = 0; i < QT; i++) {
        qv[i]  = base[(size_t)(q0 + i) * NQKV + c] * LOG2E;
        num[i] = 0.f;
        den[i] = 0.f;
    }

#pragma unroll 1
    for (int kc = 0; kc < SEQ; kc += KT) {
        __syncthreads();
#pragma unroll
        for (int r = 0; r < KT; r++) {
            ks[r][c] = base[(size_t)(kc + r) * NQKV + CH     + c];
            vs[r][c] = base[(size_t)(kc + r) * NQKV + 2 * CH + c];
        }
        __syncthreads();
#pragma unroll 3
        for (int r = 0; r < KT; r++) {
            float kk = ks[r][c];
            float vv = vs[r][c];
#pragma unroll
            for (int i = 0; i < QT; i++) {
                float e = ex2(qv[i] * kk);
                num[i] = fmaf(e, vv, num[i]);
                den[i] += e;
            }
        }
    }

    float* op = g_att + ((size_t)b * SEQ + q0) * CH + c;
#pragma unroll
    for (int i = 0; i < QT; i++) op[(size_t)i * CH] = __fdividef(num[i], den[i]);
}

// ---------------- full GEMM + relu + residual + LN stats ---------------------
// g_h += relu(g_att @ W + bias); also emit (mu, rstd) per updated row.
// tile 32M x 128N, 256 threads, per-thread 4Mx4N via f32x2 row-pairs.
__global__ void __launch_bounds__(256) full_gemm(const float* __restrict__ W,
                                                 const float* __restrict__ bias) {
    __shared__ __align__(16) float  As[16][32];
    __shared__ __align__(16) float2 Bs[16][CH];

    int tid = threadIdx.x;
    int tx = tid & 31;             // cols 4*tx
    int ty = tid >> 5;             // rows 4*ty (warp = row group)

    int arow = tid >> 3;           // 0..31
    int akh  = (tid & 7) * 2;
    int bkk  = tid >> 5;           // 0..7 (and +8)
    int bc   = (tid & 31) * 4;

    size_t rowsBase = (size_t)blockIdx.x * 32;
    const float* ap = g_att + (rowsBase + arow) * CH + akh;
    const float* bp = W + (size_t)bkk * CH + bc;

    ull acc[2][4];
#pragma unroll
    for (int p = 0; p < 2; p++)
#pragma unroll
        for (int j = 0; j < 4; j++) acc[p][j] = 0ull;

    for (int k0 = 0; k0 < CH; k0 += 16) {
        float2 a2  = *(const float2*)(ap + k0);
        float4 bv0 = *(const float4*)(bp + (size_t)k0 * CH);
        float4 bv1 = *(const float4*)(bp + (size_t)(k0 + 8) * CH);
        As[akh][arow]     = a2.x;
        As[akh + 1][arow] = a2.y;
        Bs[bkk][bc + 0] = make_float2(bv0.x, bv0.x);
        Bs[bkk][bc + 1] = make_float2(bv0.y, bv0.y);
        Bs[bkk][bc + 2] = make_float2(bv0.z, bv0.z);
        Bs[bkk][bc + 3] = make_float2(bv0.w, bv0.w);
        Bs[bkk + 8][bc + 0] = make_float2(bv1.x, bv1.x);
        Bs[bkk + 8][bc + 1] = make_float2(bv1.y, bv1.y);
        Bs[bkk + 8][bc + 2] = make_float2(bv1.z, bv1.z);
        Bs[bkk + 8][bc + 3] = make_float2(bv1.w, bv1.w);
        __syncthreads();
#pragma unroll
        for (int k = 0; k < 16; k++) {
            ulonglong2 aa  = *(const ulonglong2*)&As[k][4 * ty];
            ulonglong2 bb0 = *(const ulonglong2*)&Bs[k][4 * tx];
            ulonglong2 bb1 = *(const ulonglong2*)&Bs[k][4 * tx + 2];
            ull ap2[2] = {aa.x, aa.y};
            ull bp2[4] = {bb0.x, bb0.y, bb1.x, bb1.y};
#pragma unroll
            for (int p = 0; p < 2; p++)
#pragma unroll
                for (int j = 0; j < 4; j++)
                    acc[p][j] = fma2(ap2[p], bp2[j], acc[p][j]);
        }
        __syncthreads();
    }

    int col = 4 * tx;
    float4 bi = *(const float4*)(bias + col);
    float bb[4] = {bi.x, bi.y, bi.z, bi.w};
    float s[4], ss[4];
#pragma unroll
    for (int p = 0; p < 2; p++) {
        float lo[4], hi[4];
#pragma unroll
        for (int j = 0; j < 4; j++) upk2(acc[p][j], lo[j], hi[j]);
#pragma unroll
        for (int e = 0; e < 2; e++) {
            float* v = e ? hi : lo;
            size_t row = rowsBase + 4 * ty + 2 * p + e;
            float* hrow = g_h + row * CH + col;
            float4 old = *(const float4*)hrow;
            float h0 = old.x + fmaxf(v[0] + bb[0], 0.f);
            float h1 = old.y + fmaxf(v[1] + bb[1], 0.f);
            float h2 = old.z + fmaxf(v[2] + bb[2], 0.f);
            float h3 = old.w + fmaxf(v[3] + bb[3], 0.f);
            *(float4*)hrow = make_float4(h0, h1, h2, h3);
            int idx = 2 * p + e;
            s[idx]  = h0 + h1 + h2 + h3;
            ss[idx] = fmaf(h0, h0, fmaf(h1, h1, fmaf(h2, h2, h3 * h3)));
        }
    }
#pragma unroll
    for (int i = 0; i < 4; i++) {
#pragma unroll
        for (int o = 16; o; o >>= 1) {
            s[i]  += __shfl_xor_sync(0xffffffffu, s[i], o);
            ss[i] += __shfl_xor_sync(0xffffffffu, ss[i], o);
        }
    }
    if (tx == 0) {
#pragma unroll
        for (int i = 0; i < 4; i++) {
            size_t row = rowsBase + 4 * ty + i;
            float mu  = s[i] * (1.0f / CH);
            float var = fmaf(-mu, mu, ss[i] * (1.0f / CH));
            g_stats[row] = make_float2(mu, rsqrtf(var + EPSLN));
        }
    }
}

// ---------------- final projection: out = h @ out_w + out_b ------------------
__global__ void __launch_bounds__(256) outproj_kernel(const float* __restrict__ ow,
                                                      const float* __restrict__ ob,
                                                      float* __restrict__ out) {
    int row  = blockIdx.x * 8 + (threadIdx.x >> 5);
    int lane = threadIdx.x & 31;
    const float* hr = g_h + (size_t)row * CH;
    float a0 = 0.f, a1 = 0.f, a2 = 0.f, a3 = 0.f;
#pragma unroll
    for (int j = 0; j < 4; j++) {
        int cidx = lane + 32 * j;
        float hv = hr[cidx];
        const float* w = ow + cidx * 4;
        a0 = fmaf(hv, w[0], a0);
        a1 = fmaf(hv, w[1], a1);
        a2 = fmaf(hv, w[2], a2);
        a3 = fmaf(hv, w[3], a3);
    }
#pragma unroll
    for (int o = 16; o; o >>= 1) {
        a0 += __shfl_xor_sync(0xffffffffu, a0, o);
        a1 += __shfl_xor_sync(0xffffffffu, a1, o);
        a2 += __shfl_xor_sync(0xffffffffu, a2, o);
        a3 += __shfl_xor_sync(0xffffffffu, a3, o);
    }
    if (lane == 0) {
        *(float4*)(out + (size_t)row * 4) =
            make_float4(a0 + ob[0], a1 + ob[1], a2 + ob[2], a3 + ob[3]);
    }
}

// ---------------- launch -----------------------------------------------------
extern "C" void kernel_launch(void* const* d_in, const int* in_sizes, int n_in,
                              void* d_out, int out_size) {
    const float* x      = (const float*)d_in[0];
    const float* in_w   = (const float*)d_in[1];
    const float* in_b   = (const float*)d_in[2];
    const float* ln_g   = (const float*)d_in[3];
    const float* ln_b   = (const float*)d_in[4];
    const float* qkv_w  = (const float*)d_in[5];
    const float* qkv_b  = (const float*)d_in[6];
    const float* full_w = (const float*)d_in[7];
    const float* full_b = (const float*)d_in[8];
    const float* out_w  = (const float*)d_in[9];
    const float* out_b  = (const float*)d_in[10];
    float* out = (float*)d_out;

    inproj_kernel<<<MROWS / 8, 256>>>(x, in_w, in_b);

    for (int l = 0; l < 4; l++) {
        qkv_gemm<<<dim3(NQKV / 96, MROWS / 128), 256>>>(
            qkv_w + (size_t)l * CH * NQKV, qkv_b + l * NQKV,
            ln_g + l * CH, ln_b + l * CH);
        attn_kernel<<<dim3(SEQ / QT, TBS), 128>>>();
        full_gemm<<<MROWS / 32, 256>>>(
            full_w + (size_t)l * CH * CH, full_b + l * CH);
    }

    outproj_kernel<<<MROWS / 8, 256>>>(out_w, out_b, out);
}